// round 1
// baseline (speedup 1.0000x reference)
#include <cuda_runtime.h>
#include <cstdint>

#define EPS 1e-5f
#define NBATCH 16
#define PER (4 * 1024 * 1024)          // elements per batch (C*H*W)
#define PER4 (PER / 4)                 // float4s per batch
#define RED_THREADS 256
#define RED_BLOCKS 128                 // blocks per batch in reduction pass
#define NORM_THREADS 256
#define NORM_BLOCKS (PER4 / NORM_THREADS)  // 4096

// Scratch (allocation-free requirement -> __device__ globals)
__device__ float        g_psum[NBATCH * RED_BLOCKS];
__device__ float        g_psumsq[NBATCH * RED_BLOCKS];
__device__ unsigned int g_pcnt[NBATCH * RED_BLOCKS];
__device__ float        g_mean[NBATCH];
__device__ float        g_inv[NBATCH];

// ---------------------------------------------------------------------------
// Pass 1: per-batch partial reduction of (sum, sumsq, count of nonzeros).
// Masked entries are exactly 0.0f, so sum / sumsq over ALL elements equal the
// masked sums -> branch-free inner loop, only the count needs the compare.
// ---------------------------------------------------------------------------
__global__ __launch_bounds__(RED_THREADS)
void reduce_kernel(const float4* __restrict__ x) {
    const int b = blockIdx.y;
    const float4* xb = x + (size_t)b * PER4;

    float s = 0.f, ss = 0.f;
    unsigned int c = 0;

    const int stride = gridDim.x * blockDim.x;
    for (int i = blockIdx.x * blockDim.x + threadIdx.x; i < PER4; i += stride) {
        float4 v = xb[i];
        s  += v.x + v.y + v.z + v.w;
        ss  = fmaf(v.x, v.x, ss);
        ss  = fmaf(v.y, v.y, ss);
        ss  = fmaf(v.z, v.z, ss);
        ss  = fmaf(v.w, v.w, ss);
        c  += (v.x != 0.f) + (v.y != 0.f) + (v.z != 0.f) + (v.w != 0.f);
    }

    // warp reduce
    #pragma unroll
    for (int off = 16; off > 0; off >>= 1) {
        s  += __shfl_xor_sync(0xFFFFFFFFu, s,  off);
        ss += __shfl_xor_sync(0xFFFFFFFFu, ss, off);
        c  += __shfl_xor_sync(0xFFFFFFFFu, c,  off);
    }

    __shared__ float sh_s[RED_THREADS / 32];
    __shared__ float sh_ss[RED_THREADS / 32];
    __shared__ unsigned int sh_c[RED_THREADS / 32];
    const int lane = threadIdx.x & 31;
    const int warp = threadIdx.x >> 5;
    if (lane == 0) { sh_s[warp] = s; sh_ss[warp] = ss; sh_c[warp] = c; }
    __syncthreads();

    if (warp == 0) {
        s  = (lane < RED_THREADS / 32) ? sh_s[lane]  : 0.f;
        ss = (lane < RED_THREADS / 32) ? sh_ss[lane] : 0.f;
        c  = (lane < RED_THREADS / 32) ? sh_c[lane]  : 0u;
        #pragma unroll
        for (int off = 4; off > 0; off >>= 1) {
            s  += __shfl_xor_sync(0xFFFFFFFFu, s,  off);
            ss += __shfl_xor_sync(0xFFFFFFFFu, ss, off);
            c  += __shfl_xor_sync(0xFFFFFFFFu, c,  off);
        }
        if (lane == 0) {
            const int idx = b * gridDim.x + blockIdx.x;
            g_psum[idx]   = s;
            g_psumsq[idx] = ss;
            g_pcnt[idx]   = c;
        }
    }
}

// ---------------------------------------------------------------------------
// Pass 2: finalize per batch (one block per batch; tiny). Double accumulation.
// ---------------------------------------------------------------------------
__global__ __launch_bounds__(RED_BLOCKS)
void finalize_kernel() {
    const int b = blockIdx.x;
    const int t = threadIdx.x;

    double s = 0.0, ss = 0.0;
    unsigned long long c = 0;
    for (int i = t; i < RED_BLOCKS; i += blockDim.x) {
        s  += (double)g_psum[b * RED_BLOCKS + i];
        ss += (double)g_psumsq[b * RED_BLOCKS + i];
        c  += g_pcnt[b * RED_BLOCKS + i];
    }
    #pragma unroll
    for (int off = 16; off > 0; off >>= 1) {
        s  += __shfl_xor_sync(0xFFFFFFFFu, s,  off);
        ss += __shfl_xor_sync(0xFFFFFFFFu, ss, off);
        c  += __shfl_xor_sync(0xFFFFFFFFu, c,  off);
    }
    __shared__ double sh_s[RED_BLOCKS / 32];
    __shared__ double sh_ss[RED_BLOCKS / 32];
    __shared__ unsigned long long sh_c[RED_BLOCKS / 32];
    const int lane = t & 31, warp = t >> 5;
    if (lane == 0) { sh_s[warp] = s; sh_ss[warp] = ss; sh_c[warp] = c; }
    __syncthreads();
    if (t == 0) {
        s = 0.0; ss = 0.0; c = 0;
        for (int w = 0; w < RED_BLOCKS / 32; w++) { s += sh_s[w]; ss += sh_ss[w]; c += sh_c[w]; }
        const double n    = (double)c;
        const double mean = s / n;
        // var of centered values, unbiased; m2 term is analytically zero
        const double var  = (ss - s * s / n) / (n - 1.0);
        g_mean[b] = (float)mean;
        g_inv[b]  = (float)(1.0 / (sqrt(var) + (double)EPS));
    }
}

// ---------------------------------------------------------------------------
// Pass 3: elementwise normalize. out = valid ? (x - mean)*inv : 0 (x==0 there)
// ---------------------------------------------------------------------------
__global__ __launch_bounds__(NORM_THREADS)
void normalize_kernel(const float4* __restrict__ x, float4* __restrict__ out) {
    const int b = blockIdx.y;
    const size_t base = (size_t)b * PER4;
    const int i = blockIdx.x * blockDim.x + threadIdx.x;

    const float mean = g_mean[b];
    const float inv  = g_inv[b];

    float4 v = x[base + i];
    float4 o;
    o.x = (v.x != 0.f) ? (v.x - mean) * inv : 0.f;
    o.y = (v.y != 0.f) ? (v.y - mean) * inv : 0.f;
    o.z = (v.z != 0.f) ? (v.z - mean) * inv : 0.f;
    o.w = (v.w != 0.f) ? (v.w - mean) * inv : 0.f;
    out[base + i] = o;
}

extern "C" void kernel_launch(void* const* d_in, const int* in_sizes, int n_in,
                              void* d_out, int out_size) {
    const float4* x  = (const float4*)d_in[0];
    float4*       out = (float4*)d_out;

    dim3 redGrid(RED_BLOCKS, NBATCH);
    reduce_kernel<<<redGrid, RED_THREADS>>>(x);

    finalize_kernel<<<NBATCH, RED_BLOCKS>>>();

    dim3 normGrid(NORM_BLOCKS, NBATCH);
    normalize_kernel<<<normGrid, NORM_THREADS>>>(x, out);
}

// round 2
// speedup vs baseline: 1.0343x; 1.0343x over previous
#include <cuda_runtime.h>
#include <cstdint>

#define EPS 1e-5f
#define NBATCH 16
#define PER (4 * 1024 * 1024)          // elements per batch (C*H*W)
#define PER4 (PER / 4)                 // float4s per batch = 4M
#define RED_THREADS 256
#define RED_BLOCKS 128                 // blocks per batch in reduction pass
#define RED_STRIDE (RED_BLOCKS * RED_THREADS)      // 32768 threads per batch
#define RED_ITERS (PER4 / RED_STRIDE)              // 128 iters per thread
#define RED_UNROLL 8

#define NORM_THREADS 256
#define NORM_F4_PER_THREAD 4
#define NORM_F4_PER_BLOCK (NORM_THREADS * NORM_F4_PER_THREAD)   // 1024
#define NORM_BLOCKS (PER4 / NORM_F4_PER_BLOCK)                  // 4096 per batch

// Scratch (allocation-free requirement -> __device__ globals)
__device__ float        g_psum[NBATCH * RED_BLOCKS];
__device__ float        g_psumsq[NBATCH * RED_BLOCKS];
__device__ unsigned int g_pcnt[NBATCH * RED_BLOCKS];
__device__ float        g_mean[NBATCH];
__device__ float        g_inv[NBATCH];

// ---------------------------------------------------------------------------
// Pass 1: per-batch partial reduction of (sum, sumsq, count of nonzeros).
// Masked entries are exactly 0.0f so sum/sumsq over ALL elements equal the
// masked sums. Unrolled x8 with front-batched independent loads for MLP.
// ---------------------------------------------------------------------------
__global__ __launch_bounds__(RED_THREADS)
void reduce_kernel(const float4* __restrict__ x) {
    const int b = blockIdx.y;
    const float4* xb = x + (size_t)b * PER4;

    float s = 0.f, ss = 0.f;
    unsigned int c = 0;

    const int base = blockIdx.x * RED_THREADS + threadIdx.x;

    #pragma unroll 1
    for (int j = 0; j < RED_ITERS; j += RED_UNROLL) {
        float4 v[RED_UNROLL];
        #pragma unroll
        for (int k = 0; k < RED_UNROLL; k++)
            v[k] = xb[base + (size_t)(j + k) * RED_STRIDE];
        #pragma unroll
        for (int k = 0; k < RED_UNROLL; k++) {
            s  += v[k].x + v[k].y + v[k].z + v[k].w;
            ss  = fmaf(v[k].x, v[k].x, ss);
            ss  = fmaf(v[k].y, v[k].y, ss);
            ss  = fmaf(v[k].z, v[k].z, ss);
            ss  = fmaf(v[k].w, v[k].w, ss);
            c  += (v[k].x != 0.f) + (v[k].y != 0.f) + (v[k].z != 0.f) + (v[k].w != 0.f);
        }
    }

    // warp reduce
    #pragma unroll
    for (int off = 16; off > 0; off >>= 1) {
        s  += __shfl_xor_sync(0xFFFFFFFFu, s,  off);
        ss += __shfl_xor_sync(0xFFFFFFFFu, ss, off);
        c  += __shfl_xor_sync(0xFFFFFFFFu, c,  off);
    }

    __shared__ float sh_s[RED_THREADS / 32];
    __shared__ float sh_ss[RED_THREADS / 32];
    __shared__ unsigned int sh_c[RED_THREADS / 32];
    const int lane = threadIdx.x & 31;
    const int warp = threadIdx.x >> 5;
    if (lane == 0) { sh_s[warp] = s; sh_ss[warp] = ss; sh_c[warp] = c; }
    __syncthreads();

    if (warp == 0) {
        s  = (lane < RED_THREADS / 32) ? sh_s[lane]  : 0.f;
        ss = (lane < RED_THREADS / 32) ? sh_ss[lane] : 0.f;
        c  = (lane < RED_THREADS / 32) ? sh_c[lane]  : 0u;
        #pragma unroll
        for (int off = 4; off > 0; off >>= 1) {
            s  += __shfl_xor_sync(0xFFFFFFFFu, s,  off);
            ss += __shfl_xor_sync(0xFFFFFFFFu, ss, off);
            c  += __shfl_xor_sync(0xFFFFFFFFu, c,  off);
        }
        if (lane == 0) {
            const int idx = b * gridDim.x + blockIdx.x;
            g_psum[idx]   = s;
            g_psumsq[idx] = ss;
            g_pcnt[idx]   = c;
        }
    }
}

// ---------------------------------------------------------------------------
// Pass 2: finalize per batch (one block per batch; tiny). Double accumulation.
// ---------------------------------------------------------------------------
__global__ __launch_bounds__(RED_BLOCKS)
void finalize_kernel() {
    const int b = blockIdx.x;
    const int t = threadIdx.x;

    double s = 0.0, ss = 0.0;
    unsigned long long c = 0;
    for (int i = t; i < RED_BLOCKS; i += blockDim.x) {
        s  += (double)g_psum[b * RED_BLOCKS + i];
        ss += (double)g_psumsq[b * RED_BLOCKS + i];
        c  += g_pcnt[b * RED_BLOCKS + i];
    }
    #pragma unroll
    for (int off = 16; off > 0; off >>= 1) {
        s  += __shfl_xor_sync(0xFFFFFFFFu, s,  off);
        ss += __shfl_xor_sync(0xFFFFFFFFu, ss, off);
        c  += __shfl_xor_sync(0xFFFFFFFFu, c,  off);
    }
    __shared__ double sh_s[RED_BLOCKS / 32];
    __shared__ double sh_ss[RED_BLOCKS / 32];
    __shared__ unsigned long long sh_c[RED_BLOCKS / 32];
    const int lane = t & 31, warp = t >> 5;
    if (lane == 0) { sh_s[warp] = s; sh_ss[warp] = ss; sh_c[warp] = c; }
    __syncthreads();
    if (t == 0) {
        s = 0.0; ss = 0.0; c = 0;
        for (int w = 0; w < RED_BLOCKS / 32; w++) { s += sh_s[w]; ss += sh_ss[w]; c += sh_c[w]; }
        const double n    = (double)c;
        const double mean = s / n;
        // var of centered values, unbiased; m2 term is analytically zero
        const double var  = (ss - s * s / n) / (n - 1.0);
        g_mean[b] = (float)mean;
        g_inv[b]  = (float)(1.0 / (sqrt(var) + (double)EPS));
    }
}

// ---------------------------------------------------------------------------
// Pass 3: elementwise normalize, 4 float4s per thread with batched loads.
// Block->chunk mapping is REVERSED so we read the tail of each batch first:
// the reduce pass read those lines last, so they may still be resident in L2.
// Output uses streaming stores (__stcs) to avoid evicting reusable x lines.
// ---------------------------------------------------------------------------
__global__ __launch_bounds__(NORM_THREADS)
void normalize_kernel(const float4* __restrict__ x, float4* __restrict__ out) {
    const int b = blockIdx.y;
    const size_t base = (size_t)b * PER4;

    const int chunk = (NORM_BLOCKS - 1) - blockIdx.x;   // reversed traversal
    const size_t off = base + (size_t)chunk * NORM_F4_PER_BLOCK + threadIdx.x;

    const float mean = g_mean[b];
    const float inv  = g_inv[b];

    float4 v[NORM_F4_PER_THREAD];
    #pragma unroll
    for (int k = 0; k < NORM_F4_PER_THREAD; k++)
        v[k] = x[off + (size_t)k * NORM_THREADS];

    #pragma unroll
    for (int k = 0; k < NORM_F4_PER_THREAD; k++) {
        float4 o;
        o.x = (v[k].x != 0.f) ? (v[k].x - mean) * inv : 0.f;
        o.y = (v[k].y != 0.f) ? (v[k].y - mean) * inv : 0.f;
        o.z = (v[k].z != 0.f) ? (v[k].z - mean) * inv : 0.f;
        o.w = (v[k].w != 0.f) ? (v[k].w - mean) * inv : 0.f;
        __stcs(&out[off + (size_t)k * NORM_THREADS], o);
    }
}

extern "C" void kernel_launch(void* const* d_in, const int* in_sizes, int n_in,
                              void* d_out, int out_size) {
    const float4* x   = (const float4*)d_in[0];
    float4*       out = (float4*)d_out;

    dim3 redGrid(RED_BLOCKS, NBATCH);
    reduce_kernel<<<redGrid, RED_THREADS>>>(x);

    finalize_kernel<<<NBATCH, RED_BLOCKS>>>();

    dim3 normGrid(NORM_BLOCKS, NBATCH);
    normalize_kernel<<<normGrid, NORM_THREADS>>>(x, out);
}